// round 3
// baseline (speedup 1.0000x reference)
#include <cuda_runtime.h>

#define NN 100000
#define NE 1600000
#define C_IN 64
#define C_HID 128
#define NG 64
#define NC 10

// ---------------- scratch (__device__ globals; no allocations) ----------------
static __device__ __align__(16) float g_deg[NN];
static __device__ __align__(16) float g_dinv[NN];
static __device__ __align__(16) float g_norm[NE];
static __device__ __align__(16) int   g_src[NE];
static __device__ __align__(16) int   g_dst[NE];
static __device__ __align__(16) float g_bufA[(size_t)NN * C_HID];   // 51.2 MB
static __device__ __align__(16) float g_bufB[(size_t)NN * C_HID];   // 51.2 MB
static __device__ __align__(16) float g_pooled[NG * C_HID];
static __device__ __align__(16) float g_cnt[NG];
static __device__ int g_is64;   // 1 if index tensors are int64, 0 if int32

__device__ __forceinline__ float* bufsel(int s) { return s == 0 ? g_bufA : g_bufB; }
__device__ __forceinline__ const float* srcsel(const float* ext, int s) {
    return s < 0 ? ext : (const float*)bufsel(s);
}
// read an index element honoring runtime dtype
__device__ __forceinline__ int read_idx(const void* p, long long i) {
    if (g_is64) return (int)((const long long*)p)[i];
    return ((const int*)p)[i];
}

// ---------------- packed fp32x2 helpers (Blackwell FFMA2) ----------------
__device__ __forceinline__ unsigned long long pack2(float lo, float hi) {
    unsigned long long r;
    asm("mov.b64 %0, {%1, %2};" : "=l"(r) : "f"(lo), "f"(hi));
    return r;
}
__device__ __forceinline__ float2 unpack2(unsigned long long v) {
    float2 f;
    asm("mov.b64 {%0, %1}, %2;" : "=f"(f.x), "=f"(f.y) : "l"(v));
    return f;
}
__device__ __forceinline__ unsigned long long fma2(unsigned long long a,
                                                   unsigned long long b,
                                                   unsigned long long c) {
    unsigned long long d;
    asm("fma.rn.f32x2 %0, %1, %2, %3;" : "=l"(d) : "l"(a), "l"(b), "l"(c));
    return d;
}
// vector reduction: 4 floats in one RED op (16B-aligned address required)
__device__ __forceinline__ void red_add_v4(float* p, float a, float b, float c, float d) {
    asm volatile("red.global.add.v4.f32 [%0], {%1, %2, %3, %4};"
                 :: "l"(p), "f"(a), "f"(b), "f"(c), "f"(d) : "memory");
}

// ---------------- dtype detection ----------------
// int32 data reinterpreted as int64 packs two node ids: value >= 2^32 >> NN.
__global__ void k_detect(const void* __restrict__ ei) {
    if (threadIdx.x == 0) {
        const long long* p = (const long long*)ei;
        int ok64 = 1;
        for (int i = 0; i < 64; ++i) {
            long long v = p[i];
            if (v < 0 || v >= NN) { ok64 = 0; break; }
        }
        g_is64 = ok64;
    }
}

// ---------------- prep kernels ----------------
__global__ void k_init() {
    int t = blockIdx.x * blockDim.x + threadIdx.x;
    if (t < NN) g_deg[t] = 1.0f;                 // self-loop
    if (t < NG * C_HID) g_pooled[t] = 0.0f;
    if (t < NG) g_cnt[t] = 0.0f;
}

__global__ void k_edge_prep(const void* __restrict__ ei) {
    int e = blockIdx.x * blockDim.x + threadIdx.x;
    if (e >= NE) return;
    int s = read_idx(ei, e);
    int d = read_idx(ei, (long long)NE + e);
    s = min(max(s, 0), NN - 1);   // defensive; reference guarantees range
    d = min(max(d, 0), NN - 1);
    g_src[e] = s;
    g_dst[e] = d;
    atomicAdd(&g_deg[d], 1.0f);
}

__global__ void k_dinv() {
    int i = blockIdx.x * blockDim.x + threadIdx.x;
    if (i < NN) g_dinv[i] = rsqrtf(g_deg[i]);
}

__global__ void k_norm() {
    int e = blockIdx.x * blockDim.x + threadIdx.x;
    if (e < NE) g_norm[e] = g_dinv[g_src[e]] * g_dinv[g_dst[e]];
}

// ---------------- aggregation: self-loop init + edge scatter ----------------
// agg[i] = dinv[i]^2 * h[i]  (init), then += norm[e] * h[src[e]] for dst[e]==i
template<int C>
__global__ void k_self(const float* __restrict__ ext, int ss, int ds) {
    const float* H = srcsel(ext, ss);
    float* A = bufsel(ds);
    const int V = C / 4;
    const long long total = (long long)NN * V;
    long long gid = (long long)blockIdx.x * blockDim.x + threadIdx.x;
    long long stride = (long long)gridDim.x * blockDim.x;
    for (; gid < total; gid += stride) {
        int node = (int)(gid / V);
        float w = g_dinv[node]; w *= w;
        float4 v = ((const float4*)H)[gid];
        float4 o; o.x = w * v.x; o.y = w * v.y; o.z = w * v.z; o.w = w * v.w;
        ((float4*)A)[gid] = o;
    }
}

// one warp per edge, 128 channels = 32 lanes x float4
__global__ void k_scatter128(const float* __restrict__ ext, int ss, int ds) {
    const float* H = srcsel(ext, ss);
    float* A = bufsel(ds);
    int lane = threadIdx.x & 31;
    int warp = (blockIdx.x * blockDim.x + threadIdx.x) >> 5;
    int nwarps = (gridDim.x * blockDim.x) >> 5;
    for (int e = warp; e < NE; e += nwarps) {
        int s = g_src[e], d = g_dst[e];
        float w = g_norm[e];
        float4 v = *(const float4*)&H[(size_t)s * 128 + lane * 4];
        float* out = &A[(size_t)d * 128 + lane * 4];
        red_add_v4(out, w * v.x, w * v.y, w * v.z, w * v.w);
    }
}

// 16 lanes per edge, 64 channels
__global__ void k_scatter64(const float* __restrict__ ext, int ss, int ds) {
    const float* H = srcsel(ext, ss);
    float* A = bufsel(ds);
    long long t = (long long)blockIdx.x * blockDim.x + threadIdx.x;
    long long stride = (long long)gridDim.x * blockDim.x;
    for (long long tt = t; tt < (long long)NE * 16; tt += stride) {
        int e = (int)(tt >> 4);
        int li = (int)(tt & 15);
        int s = g_src[e], d = g_dst[e];
        float w = g_norm[e];
        float4 v = *(const float4*)&H[(size_t)s * 64 + li * 4];
        float* out = &A[(size_t)d * 64 + li * 4];
        red_add_v4(out, w * v.x, w * v.y, w * v.z, w * v.w);
    }
}

// ---------------- GEMM: Y[N x 128] = relu(X[N x K] @ W[K x 128] + b) ----------------
template<int K>
__global__ __launch_bounds__(256)
void k_gemm_bias_relu(const float* __restrict__ ext, int ss, int ds,
                      const float* __restrict__ W, const float* __restrict__ bias) {
    const float* X = srcsel(ext, ss);
    float* Y = bufsel(ds);

    __shared__ float As[64][33];
    __shared__ float Ws[32][128];

    const int tid = threadIdx.x;
    const int tx = tid & 15;       // col group: 8 cols
    const int ty = tid >> 4;       // row group: 4 rows
    const int row_base = blockIdx.x * 64;

    unsigned long long acc[4][4];
#pragma unroll
    for (int i = 0; i < 4; ++i)
#pragma unroll
        for (int j = 0; j < 4; ++j) acc[i][j] = 0ull;

    float bv[8];
#pragma unroll
    for (int j = 0; j < 8; ++j) bv[j] = __ldg(&bias[tx * 8 + j]);

    for (int k0 = 0; k0 < K; k0 += 32) {
        // load A tile 64x32 (coalesced over k)
#pragma unroll
        for (int it = 0; it < 8; ++it) {
            int i = tid + it * 256;
            int r = i >> 5, kk = i & 31;
            int grow = row_base + r;
            As[r][kk] = (grow < NN) ? X[(size_t)grow * K + (k0 + kk)] : 0.0f;
        }
        // load W tile 32x128
#pragma unroll
        for (int it = 0; it < 16; ++it) {
            int i = tid + it * 256;
            int kk = i >> 7, cc = i & 127;
            Ws[kk][cc] = W[(size_t)(k0 + kk) * C_HID + cc];
        }
        __syncthreads();

#pragma unroll 8
        for (int kk = 0; kk < 32; ++kk) {
            float4 bA = *(const float4*)&Ws[kk][tx * 8];
            float4 bB = *(const float4*)&Ws[kk][tx * 8 + 4];
            unsigned long long bp0 = pack2(bA.x, bA.y);
            unsigned long long bp1 = pack2(bA.z, bA.w);
            unsigned long long bp2 = pack2(bB.x, bB.y);
            unsigned long long bp3 = pack2(bB.z, bB.w);
#pragma unroll
            for (int i = 0; i < 4; ++i) {
                float av = As[ty * 4 + i][kk];
                unsigned long long a2 = pack2(av, av);
                acc[i][0] = fma2(a2, bp0, acc[i][0]);
                acc[i][1] = fma2(a2, bp1, acc[i][1]);
                acc[i][2] = fma2(a2, bp2, acc[i][2]);
                acc[i][3] = fma2(a2, bp3, acc[i][3]);
            }
        }
        __syncthreads();
    }

#pragma unroll
    for (int i = 0; i < 4; ++i) {
        int grow = row_base + ty * 4 + i;
        if (grow < NN) {
            float2 r0 = unpack2(acc[i][0]);
            float2 r1 = unpack2(acc[i][1]);
            float2 r2 = unpack2(acc[i][2]);
            float2 r3 = unpack2(acc[i][3]);
            float4 o0, o1;
            o0.x = fmaxf(r0.x + bv[0], 0.0f);
            o0.y = fmaxf(r0.y + bv[1], 0.0f);
            o0.z = fmaxf(r1.x + bv[2], 0.0f);
            o0.w = fmaxf(r1.y + bv[3], 0.0f);
            o1.x = fmaxf(r2.x + bv[4], 0.0f);
            o1.y = fmaxf(r2.y + bv[5], 0.0f);
            o1.z = fmaxf(r3.x + bv[6], 0.0f);
            o1.w = fmaxf(r3.y + bv[7], 0.0f);
            float* yp = &Y[(size_t)grow * C_HID + tx * 8];
            *(float4*)yp = o0;
            *(float4*)(yp + 4) = o1;
        }
    }
}

// ---------------- global mean pool (batch is sorted) ----------------
#define POOL_CHUNK 256
__global__ void k_pool(int ss, const void* __restrict__ batch) {
    const float* H = (const float*)bufsel(ss);
    __shared__ int sb[POOL_CHUNK];
    int n0 = blockIdx.x * POOL_CHUNK;
    int c = threadIdx.x;  // 0..127
    for (int i = c; i < POOL_CHUNK; i += 128) {
        int n = n0 + i;
        int g = 0;
        if (n < NN) g = read_idx(batch, n);
        g = min(max(g, 0), NG - 1);
        sb[i] = g;
    }
    __syncthreads();
    int lim = NN - n0; if (lim > POOL_CHUNK) lim = POOL_CHUNK;
    if (lim <= 0) return;
    float acc = 0.0f;
    int g = sb[0];
    int cntloc = 0;
    for (int i = 0; i < lim; ++i) {
        int gb = sb[i];
        if (gb != g) {
            atomicAdd(&g_pooled[g * C_HID + c], acc);
            if (c == 0) atomicAdd(&g_cnt[g], (float)cntloc);
            g = gb; acc = 0.0f; cntloc = 0;
        }
        acc += H[(size_t)(n0 + i) * C_HID + c];
        cntloc++;
    }
    atomicAdd(&g_pooled[g * C_HID + c], acc);
    if (c == 0) atomicAdd(&g_cnt[g], (float)cntloc);
}

// ---------------- classifier head ----------------
__global__ void k_final(const float* __restrict__ Wc, const float* __restrict__ bc,
                        float* __restrict__ out) {
    int t = threadIdx.x;
    if (t >= NG * NC) return;
    int g = t / NC, c = t % NC;
    float inv = 1.0f / fmaxf(g_cnt[g], 1.0f);
    float s = 0.0f;
#pragma unroll 16
    for (int h = 0; h < C_HID; ++h)
        s += g_pooled[g * C_HID + h] * __ldg(&Wc[h * NC + c]);
    out[t] = s * inv + bc[c];
}

// ---------------- launch ----------------
extern "C" void kernel_launch(void* const* d_in, const int* in_sizes, int n_in,
                              void* d_out, int out_size) {
    // Map inputs by element count (all distinct; the two 128-element biases
    // are interchangeable zero vectors).
    const float* x = 0; const float* W1 = 0; const float* b1 = 0;
    const float* W2 = 0; const float* b2 = 0; const float* Wc = 0;
    const float* bc = 0; const void* ei = 0; const void* batch = 0;
    for (int i = 0; i < n_in; ++i) {
        int s = in_sizes[i];
        void* p = d_in[i];
        if      (s == NN * C_IN)     x  = (const float*)p;
        else if (s == C_IN * C_HID)  W1 = (const float*)p;
        else if (s == C_HID * C_HID) W2 = (const float*)p;
        else if (s == C_HID * NC)    Wc = (const float*)p;
        else if (s == NC)            bc = (const float*)p;
        else if (s == 2 * NE)        ei = p;
        else if (s == NN)            batch = p;
        else if (s == C_HID)         { if (!b1) b1 = (const float*)p; else b2 = (const float*)p; }
    }
    if (!b2) b2 = b1;
    float* out = (float*)d_out;
    (void)out_size;

    const int T = 256;

    // dtype probe + prep
    k_detect<<<1, 32>>>(ei);
    k_init<<<(NN + T - 1) / T, T>>>();
    k_edge_prep<<<(NE + T - 1) / T, T>>>(ei);
    k_dinv<<<(NN + T - 1) / T, T>>>();
    k_norm<<<(NE + T - 1) / T, T>>>();

    // layer 1: aggregate x (64 ch) -> bufA, then GEMM -> H1 in bufB
    k_self<C_IN><<<8192, T>>>(x, -1, 0);
    k_scatter64<<<8192, T>>>(x, -1, 0);
    k_gemm_bias_relu<C_IN><<<(NN + 63) / 64, T>>>(nullptr, 0, 1, W1, b1);

    // layer 2: aggregate H1 (128 ch, bufB) -> bufA, then GEMM -> H2 in bufB
    k_self<C_HID><<<8192, T>>>(nullptr, 1, 0);
    k_scatter128<<<8192, T>>>(nullptr, 1, 0);
    k_gemm_bias_relu<C_HID><<<(NN + 63) / 64, T>>>(nullptr, 0, 1, W2, b2);

    // pool (H2 in bufB) + head
    k_pool<<<(NN + POOL_CHUNK - 1) / POOL_CHUNK, C_HID>>>(1, batch);
    k_final<<<1, 640>>>(Wc, bc, out);
}